// round 8
// baseline (speedup 1.0000x reference)
#include <cuda_runtime.h>
#include <math.h>

// Problem constants
#define B_   2
#define T_   2048
#define D_   2048
#define N_   8
#define K_   4
#define H_   256
#define WIN_ 1024
#define BT_  (B_ * T_)          // 4096
#define QKVC (N_*H_ + 2*K_*H_)  // 4096

// ---------------- device scratch (static, allocation-free) ----------------
__device__ float g_wqkv[(size_t)D_ * QKVC];   // 32 MB packed [D, 4096]
__device__ float g_qkv [(size_t)BT_ * QKVC];  // 64 MB [BT, 4096] (q|k|v)
__device__ float g_q   [(size_t)BT_ * N_*H_]; // 32 MB normalized+roped q
__device__ float g_k   [(size_t)BT_ * K_*H_]; // 16 MB normalized+roped k
__device__ float g_att [(size_t)BT_ * N_*H_]; // 32 MB attention output

// ---------------- weight packing: [D,4096] = [qw | kw | vw] ---------------
__global__ void pack_w(const float* __restrict__ qw,
                       const float* __restrict__ kw,
                       const float* __restrict__ vw) {
    unsigned idx = blockIdx.x * 256u + threadIdx.x;
    if (idx >= (unsigned)(D_ * QKVC)) return;
    unsigned d = idx >> 12;        // / 4096
    unsigned c = idx & 4095u;
    unsigned h = c & 255u;
    float v;
    if (c < 2048u)      { unsigned n = c >> 8;            v = qw[((size_t)n*D_ + d)*H_ + h]; }
    else if (c < 3072u) { unsigned n = (c - 2048u) >> 8;  v = kw[((size_t)n*D_ + d)*H_ + h]; }
    else                { unsigned n = (c - 3072u) >> 8;  v = vw[((size_t)n*D_ + d)*H_ + h]; }
    g_wqkv[idx] = v;
}

// --------------- classic 128x128x16 SGEMM, 256 thr, 8x8/thread ------------
__global__ __launch_bounds__(256)
void sgemm128(const float* __restrict__ A, const float* __restrict__ B,
              float* __restrict__ C, int M, int N, int Kd) {
    __shared__ float As[16][128];
    __shared__ float Bs[16][128];
    const int bx = blockIdx.x, by = blockIdx.y;
    const int tid = threadIdx.x;
    const int tr = tid >> 4;        // 0..15
    const int tc = tid & 15;        // 0..15
    const int aRow  = tid >> 2;     // 0..63
    const int aCol4 = (tid & 3) * 4;
    const int bRow  = tid >> 5;     // 0..7
    const int bCol4 = (tid & 31) * 4;

    const float* Ablk = A + (size_t)by * 128 * Kd;
    const float* Bblk = B + (size_t)bx * 128;
    float acc[8][8] = {};

    for (int k0 = 0; k0 < Kd; k0 += 16) {
        #pragma unroll
        for (int i = 0; i < 2; i++) {
            int r = aRow + i * 64;
            float4 a = *(const float4*)(Ablk + (size_t)r * Kd + k0 + aCol4);
            As[aCol4 + 0][r] = a.x;
            As[aCol4 + 1][r] = a.y;
            As[aCol4 + 2][r] = a.z;
            As[aCol4 + 3][r] = a.w;
        }
        #pragma unroll
        for (int i = 0; i < 2; i++) {
            int r = bRow + i * 8;
            float4 b = *(const float4*)(Bblk + (size_t)(k0 + r) * N + bCol4);
            *(float4*)(&Bs[r][bCol4]) = b;
        }
        __syncthreads();
        #pragma unroll
        for (int kk = 0; kk < 16; kk++) {
            float ra[8], rb[8];
            #pragma unroll
            for (int m = 0; m < 8; m++) ra[m] = As[kk][tr * 8 + m];
            #pragma unroll
            for (int n = 0; n < 8; n++) rb[n] = Bs[kk][tc * 8 + n];
            #pragma unroll
            for (int m = 0; m < 8; m++)
                #pragma unroll
                for (int n = 0; n < 8; n++)
                    acc[m][n] = fmaf(ra[m], rb[n], acc[m][n]);
        }
        __syncthreads();
    }
    float* Cblk = C + (size_t)(by * 128) * N + bx * 128;
    #pragma unroll
    for (int m = 0; m < 8; m++) {
        #pragma unroll
        for (int n = 0; n < 8; n += 4) {
            float4 v = make_float4(acc[m][n], acc[m][n+1], acc[m][n+2], acc[m][n+3]);
            *(float4*)(Cblk + (size_t)(tr * 8 + m) * N + tc * 8 + n) = v;
        }
    }
}

// ---------- fused RMSNorm + RoPE (+ q scaling); 1 block = (bt, head) ------
__global__ __launch_bounds__(128)
void normrope(const int* __restrict__ pos,
              const float* __restrict__ qns, const float* __restrict__ kns) {
    const int blk  = blockIdx.x;
    const int head = blk % (N_ + K_);     // 0..7 = q heads, 8..11 = k heads
    const int bt   = blk / (N_ + K_);
    const bool isq = head < N_;
    const float* src = g_qkv + (size_t)bt * QKVC +
                       (isq ? head * H_ : N_*H_ + (head - N_) * H_);
    const int i = threadIdx.x;            // 0..127, pair (i, i+128)
    float f = src[i];
    float s = src[i + 128];

    float ss = f * f + s * s;
    #pragma unroll
    for (int o = 16; o; o >>= 1) ss += __shfl_xor_sync(0xffffffffu, ss, o);
    __shared__ float red[4];
    if ((i & 31) == 0) red[i >> 5] = ss;
    __syncthreads();
    float var = (red[0] + red[1] + red[2] + red[3]) * (1.0f / 256.0f);
    float r = rsqrtf(var + 1e-6f);
    const float* ns = isq ? qns : kns;
    float fn = f * r * (1.0f + ns[i]);
    float sn = s * r * (1.0f + ns[i + 128]);

    float p  = (float)pos[bt];
    float ts = powf(10000.0f, (float)i * (1.0f / 128.0f));
    float ang = p / ts;
    float sa = sinf(ang), ca = cosf(ang);
    float o1 = fn * ca - sn * sa;
    float o2 = sn * ca + fn * sa;

    if (isq) {
        o1 *= 0.0625f; o2 *= 0.0625f;   // H^{-1/2} = 1/16
        float* dst = g_q + (size_t)bt * (N_*H_) + head * H_;
        dst[i] = o1; dst[i + 128] = o2;
    } else {
        float* dst = g_k + (size_t)bt * (K_*H_) + (head - N_) * H_;
        dst[i] = o1; dst[i + 128] = o2;
    }
}

// ================= flash attention: 64 q x 2 heads per block ===============
// M = 128 rows (row = q*2heads), key tiles of 64, 512 threads.
// smem layout (floats):
//   Qs[256][132]  Q^T tile           33792
//   Ks[16][68]    K^T chunk           1088
//   Ps[64][132]   P^T tile            8448
//   Vs[16][264]   V chunk             4224
//   rowsc[128]    per-row scale/l      128
#define QS_LD  132
#define KS_LD  68
#define PS_LD  132
#define VS_LD  264
#define SMEM_FLOATS (256*QS_LD + 16*KS_LD + 64*PS_LD + 16*VS_LD + 128)

__global__ __launch_bounds__(512, 1)
void attn_flash() {
    extern __shared__ float sm[];
    float* Qs    = sm;
    float* Ks    = Qs + 256 * QS_LD;
    float* Ps    = Ks + 16 * KS_LD;
    float* Vs    = Ps + 64 * PS_LD;
    float* rowsc = Vs + 16 * VS_LD;

    const int qt  = blockIdx.x;
    const int kvh = blockIdx.y;
    const int b   = blockIdx.z;
    const int tid = threadIdx.x;
    const int q0  = qt * 64;

    // ---- load Q tile transposed: Qs[d][r], r = (q - q0) + 64*headInGroup
    for (int idx = tid; idx < 128 * 64; idx += 512) {
        int r  = idx >> 6;          // 0..127
        int d4 = idx & 63;          // float4 index along dim
        int q    = q0 + (r & 63);
        int head = kvh * 2 + (r >> 6);
        float4 v = *(const float4*)(g_q + ((size_t)(b * T_ + q)) * (N_*H_)
                                    + head * H_ + d4 * 4);
        float* col = Qs + (d4 * 4) * QS_LD + r;
        col[0*QS_LD] = v.x; col[1*QS_LD] = v.y;
        col[2*QS_LD] = v.z; col[3*QS_LD] = v.w;
    }

    // mapping A (scores): tr rows (4), tc cols (4)
    const int tr = tid >> 4;        // 0..31
    const int tc = tid & 15;        // 0..15
    // mapping B (output): tr2 rows (8), tc2 cols (8)
    const int tr2 = tid >> 5;       // 0..15
    const int tc2 = tid & 31;       // 0..31

    float m_prev[4], l_prev[4];
    #pragma unroll
    for (int m = 0; m < 4; m++) { m_prev[m] = -1e38f; l_prev[m] = 0.f; }
    float O[8][8] = {};

    const int kt_lo = (q0 >= 1023) ? ((q0 - 1023) >> 6) : 0;
    __syncthreads();

    for (int kt = kt_lo; kt <= qt; kt++) {
        const int klo = kt << 6;

        // ---------- S = Q K^T over d-chunks of 16 ----------
        float sc[4][4] = {};
        for (int d0 = 0; d0 < 256; d0 += 16) {
            {   // load Ks[dd][c] chunk (64 keys x 16 dims), float2 per thread
                int c  = tid >> 3;          // 0..63
                int dd = (tid & 7) * 2;     // 0,2,..,14
                const float* kr = g_k + ((size_t)(b * T_ + klo + c)) * (K_*H_)
                                  + kvh * H_ + d0 + dd;
                float2 kv = *(const float2*)kr;
                Ks[dd * KS_LD + c]       = kv.x;
                Ks[(dd + 1) * KS_LD + c] = kv.y;
            }
            __syncthreads();
            #pragma unroll
            for (int kk = 0; kk < 16; kk++) {
                float4 ra4 = *(const float4*)&Qs[(d0 + kk) * QS_LD + tr * 4];
                float4 rb4 = *(const float4*)&Ks[kk * KS_LD + tc * 4];
                float ra[4] = {ra4.x, ra4.y, ra4.z, ra4.w};
                float rb[4] = {rb4.x, rb4.y, rb4.z, rb4.w};
                #pragma unroll
                for (int m = 0; m < 4; m++)
                    #pragma unroll
                    for (int n = 0; n < 4; n++)
                        sc[m][n] = fmaf(ra[m], rb[n], sc[m][n]);
            }
            __syncthreads();
        }

        // ---------- online softmax (per row, 16-lane groups) ----------
        #pragma unroll
        for (int m = 0; m < 4; m++) {
            const int q = q0 + ((tr * 4 + m) & 63);
            float rmax = -1e38f;
            #pragma unroll
            for (int n = 0; n < 4; n++) {
                int key = klo + tc * 4 + n;
                bool valid = (key <= q) && (key + WIN_ > q);
                sc[m][n] = valid ? sc[m][n] : -1e38f;
                rmax = fmaxf(rmax, sc[m][n]);
            }
            #pragma unroll
            for (int o = 8; o; o >>= 1)
                rmax = fmaxf(rmax, __shfl_xor_sync(0xffffffffu, rmax, o));
            float mnew = fmaxf(m_prev[m], rmax);
            float scl  = __expf(m_prev[m] - mnew);
            float rsum = 0.f;
            #pragma unroll
            for (int n = 0; n < 4; n++) {
                float p = (sc[m][n] > -1e37f) ? __expf(sc[m][n] - mnew) : 0.f;
                sc[m][n] = p;
                rsum += p;
            }
            #pragma unroll
            for (int o = 8; o; o >>= 1)
                rsum += __shfl_xor_sync(0xffffffffu, rsum, o);
            l_prev[m] = l_prev[m] * scl + rsum;
            m_prev[m] = mnew;
            if (tc == 0) rowsc[tr * 4 + m] = scl;
        }
        // store P^T: Ps[s][r]
        #pragma unroll
        for (int n = 0; n < 4; n++) {
            float4 pv = make_float4(sc[0][n], sc[1][n], sc[2][n], sc[3][n]);
            *(float4*)&Ps[(tc * 4 + n) * PS_LD + tr * 4] = pv;
        }
        __syncthreads();

        // ---------- O = O*scale + P V ----------
        {
            float os[8];
            #pragma unroll
            for (int mm = 0; mm < 8; mm++) os[mm] = rowsc[tr2 * 8 + mm];
            #pragma unroll
            for (int mm = 0; mm < 8; mm++)
                #pragma unroll
                for (int nn = 0; nn < 8; nn++)
                    O[mm][nn] *= os[mm];
        }
        for (int s0 = 0; s0 < 64; s0 += 16) {
            {   // load Vs[kk][d] chunk (16 keys x 256 dims)
                int kk = tid >> 5;            // 0..15
                int d8 = (tid & 31) * 8;      // 0..248
                const float* vr = g_qkv + ((size_t)(b * T_ + klo + s0 + kk)) * QKVC
                                  + (N_*H_ + K_*H_) + kvh * H_ + d8;
                float4 v0 = *(const float4*)vr;
                float4 v1 = *(const float4*)(vr + 4);
                *(float4*)&Vs[kk * VS_LD + d8]     = v0;
                *(float4*)&Vs[kk * VS_LD + d8 + 4] = v1;
            }
            __syncthreads();
            #pragma unroll
            for (int kk = 0; kk < 16; kk++) {
                const int s = s0 + kk;
                float4 p0 = *(const float4*)&Ps[s * PS_LD + tr2 * 8];
                float4 p1 = *(const float4*)&Ps[s * PS_LD + tr2 * 8 + 4];
                float4 v0 = *(const float4*)&Vs[kk * VS_LD + tc2 * 8];
                float4 v1 = *(const float4*)&Vs[kk * VS_LD + tc2 * 8 + 4];
                float pa[8] = {p0.x, p0.y, p0.z, p0.w, p1.x, p1.y, p1.z, p1.w};
                float vb[8] = {v0.x, v0.y, v0.z, v0.w, v1.x, v1.y, v1.z, v1.w};
                #pragma unroll
                for (int mm = 0; mm < 8; mm++)
                    #pragma unroll
                    for (int nn = 0; nn < 8; nn++)
                        O[mm][nn] = fmaf(pa[mm], vb[nn], O[mm][nn]);
            }
            __syncthreads();
        }
    }

    // ---------- finalize: divide by l, write out ----------
    if (tc == 0) {
        #pragma unroll
        for (int m = 0; m < 4; m++) rowsc[tr * 4 + m] = l_prev[m];
    }
    __syncthreads();
    #pragma unroll
    for (int mm = 0; mm < 8; mm++) {
        const int r = tr2 * 8 + mm;
        const float linv = 1.0f / rowsc[r];
        const int q    = q0 + (r & 63);
        const int head = kvh * 2 + (r >> 6);
        float* dst = g_att + ((size_t)(b * T_ + q)) * (N_*H_) + head * H_ + tc2 * 8;
        float4 o0 = make_float4(O[mm][0]*linv, O[mm][1]*linv, O[mm][2]*linv, O[mm][3]*linv);
        float4 o1 = make_float4(O[mm][4]*linv, O[mm][5]*linv, O[mm][6]*linv, O[mm][7]*linv);
        *(float4*)dst       = o0;
        *(float4*)(dst + 4) = o1;
    }
}

// ---------------------------------------------------------------------------
extern "C" void kernel_launch(void* const* d_in, const int* in_sizes, int n_in,
                              void* d_out, int out_size) {
    const float* x   = (const float*)d_in[0];
    const int*   pos = (const int*)  d_in[1];
    const float* q_w = (const float*)d_in[2];
    const float* k_w = (const float*)d_in[3];
    const float* v_w = (const float*)d_in[4];
    const float* o_w = (const float*)d_in[5];
    const float* qns = (const float*)d_in[6];
    const float* kns = (const float*)d_in[7];
    float* out = (float*)d_out;

    float *p_wqkv, *p_qkv, *p_att;
    cudaGetSymbolAddress((void**)&p_wqkv, g_wqkv);
    cudaGetSymbolAddress((void**)&p_qkv,  g_qkv);
    cudaGetSymbolAddress((void**)&p_att,  g_att);

    const int smem_bytes = SMEM_FLOATS * sizeof(float);  // ~186 KB
    cudaFuncSetAttribute(attn_flash,
                         cudaFuncAttributeMaxDynamicSharedMemorySize, smem_bytes);

    // 1) pack weights into [D, 4096]
    pack_w<<<(D_ * QKVC + 255) / 256, 256>>>(q_w, k_w, v_w);

    // 2) QKV projection: [4096,2048] x [2048,4096]
    dim3 g1(QKVC / 128, BT_ / 128);
    sgemm128<<<g1, 256>>>(x, p_wqkv, p_qkv, BT_, QKVC, D_);

    // 3) RMSNorm + RoPE + q scaling
    normrope<<<BT_ * (N_ + K_), 128>>>(pos, qns, kns);

    // 4) flash sliding-window attention
    attn_flash<<<dim3(T_ / 64, K_, B_), 512, smem_bytes>>>();

    // 5) O projection: [4096,2048] x [2048,2048] -> d_out
    dim3 g2(D_ / 128, BT_ / 128);
    sgemm128<<<g2, 256>>>(p_att, o_w, out, BT_, D_, N_ * H_);
}

// round 10
// speedup vs baseline: 1.0028x; 1.0028x over previous
#include <cuda_runtime.h>
#include <math.h>

// Problem constants
#define B_   2
#define T_   2048
#define D_   2048
#define N_   8
#define K_   4
#define H_   256
#define WIN_ 1024
#define BT_  (B_ * T_)          // 4096
#define QKVC (N_*H_ + 2*K_*H_)  // 4096

// ---------------- device scratch (static, allocation-free) ----------------
__device__ float g_wqkv[(size_t)D_ * QKVC];   // 32 MB packed [D, 4096]
__device__ float g_qkv [(size_t)BT_ * QKVC];  // 64 MB [BT, 4096] (q|k|v)
__device__ float g_q   [(size_t)BT_ * N_*H_]; // 32 MB normalized+roped q
__device__ float g_k   [(size_t)BT_ * K_*H_]; // 16 MB normalized+roped k
__device__ float g_att [(size_t)BT_ * N_*H_]; // 32 MB attention output

// ---------------- weight packing: [D,4096] = [qw | kw | vw] ---------------
__global__ void pack_w(const float* __restrict__ qw,
                       const float* __restrict__ kw,
                       const float* __restrict__ vw) {
    unsigned idx = blockIdx.x * 256u + threadIdx.x;
    if (idx >= (unsigned)(D_ * QKVC)) return;
    unsigned d = idx >> 12;        // / 4096
    unsigned c = idx & 4095u;
    unsigned h = c & 255u;
    float v;
    if (c < 2048u)      { unsigned n = c >> 8;            v = qw[((size_t)n*D_ + d)*H_ + h]; }
    else if (c < 3072u) { unsigned n = (c - 2048u) >> 8;  v = kw[((size_t)n*D_ + d)*H_ + h]; }
    else                { unsigned n = (c - 3072u) >> 8;  v = vw[((size_t)n*D_ + d)*H_ + h]; }
    g_wqkv[idx] = v;
}

// --------------- classic 128x128x16 SGEMM, 256 thr, 8x8/thread ------------
__global__ __launch_bounds__(256)
void sgemm128(const float* __restrict__ A, const float* __restrict__ B,
              float* __restrict__ C, int M, int N, int Kd) {
    __shared__ float As[16][128];
    __shared__ float Bs[16][128];
    const int bx = blockIdx.x, by = blockIdx.y;
    const int tid = threadIdx.x;
    const int tr = tid >> 4;        // 0..15
    const int tc = tid & 15;        // 0..15
    const int aRow  = tid >> 2;     // 0..63
    const int aCol4 = (tid & 3) * 4;
    const int bRow  = tid >> 5;     // 0..7
    const int bCol4 = (tid & 31) * 4;

    const float* Ablk = A + (size_t)by * 128 * Kd;
    const float* Bblk = B + (size_t)bx * 128;
    float acc[8][8] = {};

    for (int k0 = 0; k0 < Kd; k0 += 16) {
        #pragma unroll
        for (int i = 0; i < 2; i++) {
            int r = aRow + i * 64;
            float4 a = *(const float4*)(Ablk + (size_t)r * Kd + k0 + aCol4);
            As[aCol4 + 0][r] = a.x;
            As[aCol4 + 1][r] = a.y;
            As[aCol4 + 2][r] = a.z;
            As[aCol4 + 3][r] = a.w;
        }
        #pragma unroll
        for (int i = 0; i < 2; i++) {
            int r = bRow + i * 8;
            float4 b = *(const float4*)(Bblk + (size_t)(k0 + r) * N + bCol4);
            *(float4*)(&Bs[r][bCol4]) = b;
        }
        __syncthreads();
        #pragma unroll
        for (int kk = 0; kk < 16; kk++) {
            float ra[8], rb[8];
            #pragma unroll
            for (int m = 0; m < 8; m++) ra[m] = As[kk][tr * 8 + m];
            #pragma unroll
            for (int n = 0; n < 8; n++) rb[n] = Bs[kk][tc * 8 + n];
            #pragma unroll
            for (int m = 0; m < 8; m++)
                #pragma unroll
                for (int n = 0; n < 8; n++)
                    acc[m][n] = fmaf(ra[m], rb[n], acc[m][n]);
        }
        __syncthreads();
    }
    float* Cblk = C + (size_t)(by * 128) * N + bx * 128;
    #pragma unroll
    for (int m = 0; m < 8; m++) {
        #pragma unroll
        for (int n = 0; n < 8; n += 4) {
            float4 v = make_float4(acc[m][n], acc[m][n+1], acc[m][n+2], acc[m][n+3]);
            *(float4*)(Cblk + (size_t)(tr * 8 + m) * N + tc * 8 + n) = v;
        }
    }
}

// ---------- fused RMSNorm + RoPE (+ q scaling); 1 block = (bt, head) ------
__global__ __launch_bounds__(128)
void normrope(const int* __restrict__ pos,
              const float* __restrict__ qns, const float* __restrict__ kns) {
    const int blk  = blockIdx.x;
    const int head = blk % (N_ + K_);     // 0..7 = q heads, 8..11 = k heads
    const int bt   = blk / (N_ + K_);
    const bool isq = head < N_;
    const float* src = g_qkv + (size_t)bt * QKVC +
                       (isq ? head * H_ : N_*H_ + (head - N_) * H_);
    const int i = threadIdx.x;            // 0..127, pair (i, i+128)
    float f = src[i];
    float s = src[i + 128];

    float ss = f * f + s * s;
    #pragma unroll
    for (int o = 16; o; o >>= 1) ss += __shfl_xor_sync(0xffffffffu, ss, o);
    __shared__ float red[4];
    if ((i & 31) == 0) red[i >> 5] = ss;
    __syncthreads();
    float var = (red[0] + red[1] + red[2] + red[3]) * (1.0f / 256.0f);
    float r = rsqrtf(var + 1e-6f);
    const float* ns = isq ? qns : kns;
    float fn = f * r * (1.0f + ns[i]);
    float sn = s * r * (1.0f + ns[i + 128]);

    float p  = (float)pos[bt];
    float ts = powf(10000.0f, (float)i * (1.0f / 128.0f));
    float ang = p / ts;
    float sa = sinf(ang), ca = cosf(ang);
    float o1 = fn * ca - sn * sa;
    float o2 = sn * ca + fn * sa;

    if (isq) {
        o1 *= 0.0625f; o2 *= 0.0625f;   // H^{-1/2} = 1/16
        float* dst = g_q + (size_t)bt * (N_*H_) + head * H_;
        dst[i] = o1; dst[i + 128] = o2;
    } else {
        float* dst = g_k + (size_t)bt * (K_*H_) + (head - N_) * H_;
        dst[i] = o1; dst[i + 128] = o2;
    }
}

// ================= flash attention: 64 q x 2 heads per block ===============
// M = 128 rows (row = q*2heads), key tiles of 64, 512 threads.
// smem layout (floats):
//   Qs[256][132]  Q^T tile           33792
//   Ks[16][68]    K^T chunk           1088
//   Ps[64][132]   P^T tile            8448
//   Vs[16][264]   V chunk             4224
//   rowsc[128]    per-row scale/l      128
#define QS_LD  132
#define KS_LD  68
#define PS_LD  132
#define VS_LD  264
#define SMEM_FLOATS (256*QS_LD + 16*KS_LD + 64*PS_LD + 16*VS_LD + 128)

__global__ __launch_bounds__(512, 1)
void attn_flash() {
    extern __shared__ float sm[];
    float* Qs    = sm;
    float* Ks    = Qs + 256 * QS_LD;
    float* Ps    = Ks + 16 * KS_LD;
    float* Vs    = Ps + 64 * PS_LD;
    float* rowsc = Vs + 16 * VS_LD;

    const int qt  = blockIdx.x;
    const int kvh = blockIdx.y;
    const int b   = blockIdx.z;
    const int tid = threadIdx.x;
    const int q0  = qt * 64;

    // ---- load Q tile transposed: Qs[d][r], r = (q - q0) + 64*headInGroup
    for (int idx = tid; idx < 128 * 64; idx += 512) {
        int r  = idx >> 6;          // 0..127
        int d4 = idx & 63;          // float4 index along dim
        int q    = q0 + (r & 63);
        int head = kvh * 2 + (r >> 6);
        float4 v = *(const float4*)(g_q + ((size_t)(b * T_ + q)) * (N_*H_)
                                    + head * H_ + d4 * 4);
        float* col = Qs + (d4 * 4) * QS_LD + r;
        col[0*QS_LD] = v.x; col[1*QS_LD] = v.y;
        col[2*QS_LD] = v.z; col[3*QS_LD] = v.w;
    }

    // mapping A (scores): tr rows (4), tc cols (4)
    const int tr = tid >> 4;        // 0..31
    const int tc = tid & 15;        // 0..15
    // mapping B (output): tr2 rows (8), tc2 cols (8)
    const int tr2 = tid >> 5;       // 0..15
    const int tc2 = tid & 31;       // 0..31

    float m_prev[4], l_prev[4];
    #pragma unroll
    for (int m = 0; m < 4; m++) { m_prev[m] = -1e38f; l_prev[m] = 0.f; }
    float O[8][8] = {};

    const int kt_lo = (q0 >= 1023) ? ((q0 - 1023) >> 6) : 0;
    __syncthreads();

    for (int kt = kt_lo; kt <= qt; kt++) {
        const int klo = kt << 6;

        // ---------- S = Q K^T over d-chunks of 16 ----------
        float sc[4][4] = {};
        for (int d0 = 0; d0 < 256; d0 += 16) {
            {   // load Ks[dd][c] chunk (64 keys x 16 dims), float2 per thread
                int c  = tid >> 3;          // 0..63
                int dd = (tid & 7) * 2;     // 0,2,..,14
                const float* kr = g_k + ((size_t)(b * T_ + klo + c)) * (K_*H_)
                                  + kvh * H_ + d0 + dd;
                float2 kv = *(const float2*)kr;
                Ks[dd * KS_LD + c]       = kv.x;
                Ks[(dd + 1) * KS_LD + c] = kv.y;
            }
            __syncthreads();
            #pragma unroll
            for (int kk = 0; kk < 16; kk++) {
                float4 ra4 = *(const float4*)&Qs[(d0 + kk) * QS_LD + tr * 4];
                float4 rb4 = *(const float4*)&Ks[kk * KS_LD + tc * 4];
                float ra[4] = {ra4.x, ra4.y, ra4.z, ra4.w};
                float rb[4] = {rb4.x, rb4.y, rb4.z, rb4.w};
                #pragma unroll
                for (int m = 0; m < 4; m++)
                    #pragma unroll
                    for (int n = 0; n < 4; n++)
                        sc[m][n] = fmaf(ra[m], rb[n], sc[m][n]);
            }
            __syncthreads();
        }

        // ---------- online softmax (per row, 16-lane groups) ----------
        #pragma unroll
        for (int m = 0; m < 4; m++) {
            const int q = q0 + ((tr * 4 + m) & 63);
            float rmax = -1e38f;
            #pragma unroll
            for (int n = 0; n < 4; n++) {
                int key = klo + tc * 4 + n;
                bool valid = (key <= q) && (key + WIN_ > q);
                sc[m][n] = valid ? sc[m][n] : -1e38f;
                rmax = fmaxf(rmax, sc[m][n]);
            }
            #pragma unroll
            for (int o = 8; o; o >>= 1)
                rmax = fmaxf(rmax, __shfl_xor_sync(0xffffffffu, rmax, o));
            float mnew = fmaxf(m_prev[m], rmax);
            float scl  = __expf(m_prev[m] - mnew);
            float rsum = 0.f;
            #pragma unroll
            for (int n = 0; n < 4; n++) {
                float p = (sc[m][n] > -1e37f) ? __expf(sc[m][n] - mnew) : 0.f;
                sc[m][n] = p;
                rsum += p;
            }
            #pragma unroll
            for (int o = 8; o; o >>= 1)
                rsum += __shfl_xor_sync(0xffffffffu, rsum, o);
            l_prev[m] = l_prev[m] * scl + rsum;
            m_prev[m] = mnew;
            if (tc == 0) rowsc[tr * 4 + m] = scl;
        }
        // store P^T: Ps[s][r]
        #pragma unroll
        for (int n = 0; n < 4; n++) {
            float4 pv = make_float4(sc[0][n], sc[1][n], sc[2][n], sc[3][n]);
            *(float4*)&Ps[(tc * 4 + n) * PS_LD + tr * 4] = pv;
        }
        __syncthreads();

        // ---------- O = O*scale + P V ----------
        {
            float os[8];
            #pragma unroll
            for (int mm = 0; mm < 8; mm++) os[mm] = rowsc[tr2 * 8 + mm];
            #pragma unroll
            for (int mm = 0; mm < 8; mm++)
                #pragma unroll
                for (int nn = 0; nn < 8; nn++)
                    O[mm][nn] *= os[mm];
        }
        for (int s0 = 0; s0 < 64; s0 += 16) {
            {   // load Vs[kk][d] chunk (16 keys x 256 dims)
                int kk = tid >> 5;            // 0..15
                int d8 = (tid & 31) * 8;      // 0..248
                const float* vr = g_qkv + ((size_t)(b * T_ + klo + s0 + kk)) * QKVC
                                  + (N_*H_ + K_*H_) + kvh * H_ + d8;
                float4 v0 = *(const float4*)vr;
                float4 v1 = *(const float4*)(vr + 4);
                *(float4*)&Vs[kk * VS_LD + d8]     = v0;
                *(float4*)&Vs[kk * VS_LD + d8 + 4] = v1;
            }
            __syncthreads();
            #pragma unroll
            for (int kk = 0; kk < 16; kk++) {
                const int s = s0 + kk;
                float4 p0 = *(const float4*)&Ps[s * PS_LD + tr2 * 8];
                float4 p1 = *(const float4*)&Ps[s * PS_LD + tr2 * 8 + 4];
                float4 v0 = *(const float4*)&Vs[kk * VS_LD + tc2 * 8];
                float4 v1 = *(const float4*)&Vs[kk * VS_LD + tc2 * 8 + 4];
                float pa[8] = {p0.x, p0.y, p0.z, p0.w, p1.x, p1.y, p1.z, p1.w};
                float vb[8] = {v0.x, v0.y, v0.z, v0.w, v1.x, v1.y, v1.z, v1.w};
                #pragma unroll
                for (int mm = 0; mm < 8; mm++)
                    #pragma unroll
                    for (int nn = 0; nn < 8; nn++)
                        O[mm][nn] = fmaf(pa[mm], vb[nn], O[mm][nn]);
            }
            __syncthreads();
        }
    }

    // ---------- finalize: divide by l, write out ----------
    if (tc == 0) {
        #pragma unroll
        for (int m = 0; m < 4; m++) rowsc[tr * 4 + m] = l_prev[m];
    }
    __syncthreads();
    #pragma unroll
    for (int mm = 0; mm < 8; mm++) {
        const int r = tr2 * 8 + mm;
        const float linv = 1.0f / rowsc[r];
        const int q    = q0 + (r & 63);
        const int head = kvh * 2 + (r >> 6);
        float* dst = g_att + ((size_t)(b * T_ + q)) * (N_*H_) + head * H_ + tc2 * 8;
        float4 o0 = make_float4(O[mm][0]*linv, O[mm][1]*linv, O[mm][2]*linv, O[mm][3]*linv);
        float4 o1 = make_float4(O[mm][4]*linv, O[mm][5]*linv, O[mm][6]*linv, O[mm][7]*linv);
        *(float4*)dst       = o0;
        *(float4*)(dst + 4) = o1;
    }
}

// ---------------------------------------------------------------------------
extern "C" void kernel_launch(void* const* d_in, const int* in_sizes, int n_in,
                              void* d_out, int out_size) {
    const float* x   = (const float*)d_in[0];
    const int*   pos = (const int*)  d_in[1];
    const float* q_w = (const float*)d_in[2];
    const float* k_w = (const float*)d_in[3];
    const float* v_w = (const float*)d_in[4];
    const float* o_w = (const float*)d_in[5];
    const float* qns = (const float*)d_in[6];
    const float* kns = (const float*)d_in[7];
    float* out = (float*)d_out;

    float *p_wqkv, *p_qkv, *p_att;
    cudaGetSymbolAddress((void**)&p_wqkv, g_wqkv);
    cudaGetSymbolAddress((void**)&p_qkv,  g_qkv);
    cudaGetSymbolAddress((void**)&p_att,  g_att);

    const int smem_bytes = SMEM_FLOATS * sizeof(float);  // ~186 KB
    cudaFuncSetAttribute(attn_flash,
                         cudaFuncAttributeMaxDynamicSharedMemorySize, smem_bytes);

    // 1) pack weights into [D, 4096]
    pack_w<<<(D_ * QKVC + 255) / 256, 256>>>(q_w, k_w, v_w);

    // 2) QKV projection: [4096,2048] x [2048,4096]
    dim3 g1(QKVC / 128, BT_ / 128);
    sgemm128<<<g1, 256>>>(x, p_wqkv, p_qkv, BT_, QKVC, D_);

    // 3) RMSNorm + RoPE + q scaling
    normrope<<<BT_ * (N_ + K_), 128>>>(pos, qns, kns);

    // 4) flash sliding-window attention
    attn_flash<<<dim3(T_ / 64, K_, B_), 512, smem_bytes>>>();

    // 5) O projection: [4096,2048] x [2048,2048] -> d_out
    dim3 g2(D_ / 128, BT_ / 128);
    sgemm128<<<g2, 256>>>(p_att, o_w, out, BT_, D_, N_ * H_);
}